// round 13
// baseline (speedup 1.0000x reference)
#include <cuda_runtime.h>
#include <cuda_fp16.h>
#include <cstdint>
#include <math.h>

// ---------------------------------------------------------------------------
// Problem constants
// ---------------------------------------------------------------------------
#define BB    8
#define SS    512
#define DD    512
#define WID   16
#define NN    (SS + 2 * WID)      // 544
#define MQ    (BB * NN)           // 4352
#define MH    (BB * SS)           // 4096
#define KDIM  512
#define WINSZ (WID + 2)           // 18

// GEMM tiling: 128x256 CTA tile, warp 64x64 (2x4 grid), BK=32, 4-stage ring
#define STRH     40                         // smem row stride in halfs
#define A_ST     (128 * STRH * 2)           // 10240
#define W_ST     (256 * STRH * 2)           // 20480
#define STG_BYTES (A_ST + W_ST)             // 30720
#define NSTG     4
#define DYN_SMEM (NSTG * STG_BYTES)         // 122880

// ---------------------------------------------------------------------------
// Scratch (static device memory; allocation is forbidden)
// ---------------------------------------------------------------------------
__device__ __half g_X[MQ * DD];
__device__ __half g_QKVcat[MQ * 3072];
__device__ __half g_ATT0[MQ * DD];
__device__ __half g_ATT1[MQ * DD];
__device__ __half g_HX0[MH * DD];
__device__ __half g_HX1[MH * DD];
__device__ __half g_HY0[MH * DD];
__device__ __half g_HY1[MH * DD];
// fp16 weights, packed (half units):
//  [0]        l_Wqkv  1536*512
//  [786432]   r_Wqkv
//  [1572864]  l_Wo     512*512
//  [1835008]  r_Wo
//  [2097152]  lhw_W   2*1024*512  (rows interleaved: 2c=proj_c, 2c+1=gate_c)
//  [3145728]  rhw_W
__device__ __half g_WC[4194304];
// fp32 biases: [0..3071] qkv cat (l then r); [3072..7167] hw interleaved
__device__ float g_B[7168];

// ---------------------------------------------------------------------------
// Convert weights to fp16, packed into g_WC
// ---------------------------------------------------------------------------
__global__ void convert_weights_kernel(const float* __restrict__ lqkv,
                                       const float* __restrict__ rqkv,
                                       const float* __restrict__ lwo,
                                       const float* __restrict__ rwo,
                                       const float* __restrict__ lhw,
                                       const float* __restrict__ rhw,
                                       __half* __restrict__ out) {
    int t = blockIdx.x * blockDim.x + threadIdx.x;
    if (t >= 1048576) return;
    const float* src;
    int loc;
    if (t < 196608)      { src = lqkv; loc = t; }
    else if (t < 393216) { src = rqkv; loc = t - 196608; }
    else if (t < 458752) { src = lwo;  loc = t - 393216; }
    else if (t < 524288) { src = rwo;  loc = t - 458752; }
    else {
        int u = t - 524288;
        int side  = u / 262144;
        int v     = u % 262144;
        int layer = v / 131072;
        int w     = v % 131072;
        int j     = w / 128;           // dest row (interleaved proj/gate)
        int c4    = w % 128;
        int srow  = (j & 1) ? (512 + (j >> 1)) : (j >> 1);
        src = side ? rhw : lhw;
        loc = layer * 131072 + srow * 128 + c4;
    }
    float4 v = reinterpret_cast<const float4*>(src)[loc];
    __half2 h0 = __floats2half2_rn(v.x, v.y);
    __half2 h1 = __floats2half2_rn(v.z, v.w);
    uint2 pk = make_uint2(*(uint32_t*)&h0, *(uint32_t*)&h1);
    *reinterpret_cast<uint2*>(out + (size_t)t * 4) = pk;
}

__global__ void bias_cat_kernel(const float* __restrict__ lbq,
                                const float* __restrict__ rbq,
                                const float* __restrict__ lhb,
                                const float* __restrict__ rhb,
                                float* __restrict__ B) {
    int t = blockIdx.x * blockDim.x + threadIdx.x;
    if (t >= 7168) return;
    if (t < 1536)       B[t] = lbq[t];
    else if (t < 3072)  B[t] = rbq[t - 1536];
    else {
        int u = t - 3072;
        int side  = u >> 11;
        int layer = (u >> 10) & 1;
        int j     = u & 1023;
        int c     = j >> 1;
        int srcj  = (j & 1) ? (512 + c) : c;
        const float* hb = side ? rhb : lhb;
        B[t] = hb[layer * 1024 + srcj];
    }
}

// ---------------------------------------------------------------------------
// Padded input -> fp16
// ---------------------------------------------------------------------------
__global__ void pad_kernel(const float* __restrict__ inp,
                           const float* __restrict__ lp,
                           const float* __restrict__ rp,
                           __half* __restrict__ X) {
    int t = blockIdx.x * blockDim.x + threadIdx.x;     // float4 index
    const int TOT = MQ * (DD / 4);
    if (t >= TOT) return;
    int row = t / (DD / 4);
    int c4  = t % (DD / 4);
    int b = row / NN;
    int n = row % NN;
    float4 v;
    if (n < WID) {
        v = reinterpret_cast<const float4*>(lp)[n * (DD / 4) + c4];
    } else if (n >= WID + SS) {
        v = reinterpret_cast<const float4*>(rp)[(n - WID - SS) * (DD / 4) + c4];
    } else {
        v = reinterpret_cast<const float4*>(inp)[((size_t)b * SS + (n - WID)) * (DD / 4) + c4];
    }
    __half2 h0 = __floats2half2_rn(v.x, v.y);
    __half2 h1 = __floats2half2_rn(v.z, v.w);
    uint2 pk = make_uint2(*(uint32_t*)&h0, *(uint32_t*)&h1);
    *reinterpret_cast<uint2*>(X + (size_t)t * 4) = pk;
}

// ---------------------------------------------------------------------------
// FP16 mma.sync GEMM: C[M, Nt] = A[M,512]h @ W[Nt,512]h^T (f32 accum).
// CTA tile 128x256, 8 warps as 2(M) x 4(N), warp tile 64x64, BK=32,
// 4-stage cp.async ring, one __syncthreads per K-step, ldmatrix loads.
//   mode 0: C(half) = acc + bias                  (stride Nt)
//   mode 1: Wo + row-slice [WID,WID+SS) -> C(half, stride 512)
//   mode 2: highway (interleaved proj/gate cols) -> C(half, stride 512)
//   mode 3: highway -> final output, fp32, both tuple copies (aux=out_size)
// blockIdx.z selects side.
// ---------------------------------------------------------------------------
__global__ __launch_bounds__(256, 1) void gemm_fused_kernel(
    const __half* __restrict__ A0, const __half* __restrict__ A1,
    const __half* __restrict__ W0, const __half* __restrict__ W1,
    const float* __restrict__ B0, const float* __restrict__ B1,
    void* __restrict__ C0, void* __restrict__ C1,
    int Nt, int mode, int aux) {
    extern __shared__ char dsm[];

    const int z = blockIdx.z;
    const __half* A = z ? A1 : A0;
    const __half* W = z ? W1 : W0;
    const float* bias = z ? B1 : B0;
    void* C = z ? C1 : C0;

    const int bm = blockIdx.y * 128;
    const int bn = blockIdx.x * 256;
    const int tid = threadIdx.x;
    const int lane = tid & 31;
    const int wrp = tid >> 5;
    const int wm = (wrp & 1) * 64;     // warp m offset (2 rows)
    const int wn = (wrp >> 1) * 64;    // warp n offset (4 cols)
    const int g  = lane >> 2;          // epilogue row within 8
    const int tg = lane & 3;

    const uint32_t smemBase = (uint32_t)__cvta_generic_to_shared(dsm);

    // ldmatrix provider byte offsets
    const uint32_t aOff =
        ((wm + (lane & 15)) * STRH + (lane >> 4) * 8) * 2;
    const uint32_t bOff =
        ((wn + ((lane >> 4) & 1) * 8 + (lane & 7)) * STRH + ((lane >> 3) & 1) * 8) * 2;

    float acc[4][8][4];
#pragma unroll
    for (int mt = 0; mt < 4; mt++)
#pragma unroll
        for (int nt = 0; nt < 8; nt++)
#pragma unroll
            for (int r = 0; r < 4; r++) acc[mt][nt][r] = 0.0f;

    // global->smem per stage: A 512 chunks (16B), W 1024 chunks; 6/thread
    auto issue = [&](int s, int k0) {
        uint32_t base = smemBase + s * STG_BYTES;
#pragma unroll
        for (int i = 0; i < 2; i++) {
            int id = tid + (i << 8);
            int r = id >> 2, c = id & 3;
            uint32_t dst = base + (r * STRH + c * 8) * 2;
            const __half* src = A + (size_t)(bm + r) * KDIM + k0 + c * 8;
            asm volatile("cp.async.cg.shared.global [%0], [%1], 16;"
                         :: "r"(dst), "l"(src));
        }
#pragma unroll
        for (int i = 0; i < 4; i++) {
            int id = tid + (i << 8);
            int r = id >> 2, c = id & 3;
            uint32_t dst = base + A_ST + (r * STRH + c * 8) * 2;
            const __half* src = W + (size_t)(bn + r) * KDIM + k0 + c * 8;
            asm volatile("cp.async.cg.shared.global [%0], [%1], 16;"
                         :: "r"(dst), "l"(src));
        }
        asm volatile("cp.async.commit_group;");
    };

    auto compute = [&](int s) {
        const uint32_t aPtr = smemBase + s * STG_BYTES + aOff;
        const uint32_t wPtr = smemBase + s * STG_BYTES + A_ST + bOff;
#pragma unroll
        for (int kc = 0; kc < 2; kc++) {           // two k16 chunks in BK=32
            uint32_t a[4][4], b[8][2];
#pragma unroll
            for (int mt = 0; mt < 4; mt++) {
                uint32_t addr = aPtr + mt * (16 * STRH * 2) + kc * 32;
                asm volatile(
                    "ldmatrix.sync.aligned.m8n8.x4.shared.b16 {%0,%1,%2,%3}, [%4];"
                    : "=r"(a[mt][0]), "=r"(a[mt][1]), "=r"(a[mt][2]),
                      "=r"(a[mt][3])
                    : "r"(addr));
            }
#pragma unroll
            for (int ntp = 0; ntp < 4; ntp++) {
                uint32_t addr = wPtr + ntp * (16 * STRH * 2) + kc * 32;
                asm volatile(
                    "ldmatrix.sync.aligned.m8n8.x4.shared.b16 {%0,%1,%2,%3}, [%4];"
                    : "=r"(b[2 * ntp][0]), "=r"(b[2 * ntp][1]),
                      "=r"(b[2 * ntp + 1][0]), "=r"(b[2 * ntp + 1][1])
                    : "r"(addr));
            }
#pragma unroll
            for (int mt = 0; mt < 4; mt++)
#pragma unroll
                for (int nt = 0; nt < 8; nt++)
                    asm volatile(
                        "mma.sync.aligned.m16n8k16.row.col.f32.f16.f16.f32 "
                        "{%0,%1,%2,%3},{%4,%5,%6,%7},{%8,%9},{%0,%1,%2,%3};"
                        : "+f"(acc[mt][nt][0]), "+f"(acc[mt][nt][1]),
                          "+f"(acc[mt][nt][2]), "+f"(acc[mt][nt][3])
                        : "r"(a[mt][0]), "r"(a[mt][1]), "r"(a[mt][2]),
                          "r"(a[mt][3]), "r"(b[nt][0]), "r"(b[nt][1]));
        }
    };

    const int NIT = KDIM / 32;   // 16
    issue(0, 0);
    issue(1, 32);
    issue(2, 64);
    for (int it = 0; it < NIT; it++) {
        if (it < NIT - 3)
            asm volatile("cp.async.wait_group 2;");
        else
            asm volatile("cp.async.wait_group 0;");
        __syncthreads();
        if (it + 3 < NIT) issue((it + 3) & 3, (it + 3) * 32);
        compute(it & 3);
    }

    // ---------------- epilogues ----------------
    if (mode == 0) {
        __half* Ch = (__half*)C;
#pragma unroll
        for (int mt = 0; mt < 4; mt++) {
            int r0 = bm + wm + mt * 16 + g;
#pragma unroll
            for (int nt = 0; nt < 8; nt++) {
                int c = bn + wn + nt * 8 + tg * 2;
                float b0 = bias[c], b1 = bias[c + 1];
                __half2 v0 = __floats2half2_rn(acc[mt][nt][0] + b0,
                                               acc[mt][nt][1] + b1);
                __half2 v1 = __floats2half2_rn(acc[mt][nt][2] + b0,
                                               acc[mt][nt][3] + b1);
                *reinterpret_cast<__half2*>(&Ch[(size_t)r0 * Nt + c]) = v0;
                *reinterpret_cast<__half2*>(&Ch[(size_t)(r0 + 8) * Nt + c]) = v1;
            }
        }
    } else if (mode == 1) {
        // Wo + slice: row r -> (b, n); keep n in [WID, WID+SS); half out
        __half* Ch = (__half*)C;
#pragma unroll
        for (int mt = 0; mt < 4; mt++) {
            int r0 = bm + wm + mt * 16 + g;
#pragma unroll
            for (int half_r = 0; half_r < 2; half_r++) {
                int r = r0 + half_r * 8;
                int b = r / NN;
                int n = r % NN;
                if (n < WID || n >= WID + SS) continue;
                int drow = b * SS + (n - WID);
#pragma unroll
                for (int nt = 0; nt < 8; nt++) {
                    int c = bn + wn + nt * 8 + tg * 2;
                    float b0 = bias[c], b1 = bias[c + 1];
                    __half2 v = __floats2half2_rn(
                        acc[mt][nt][0 + 2 * half_r] + b0,
                        acc[mt][nt][1 + 2 * half_r] + b1);
                    *reinterpret_cast<__half2*>(&Ch[(size_t)drow * DD + c]) = v;
                }
            }
        }
    } else if (mode == 2) {
        // highway: acc pair = (proj, gate) for channel col/2; x_old = A (half)
        __half* Ch = (__half*)C;
#pragma unroll
        for (int mt = 0; mt < 4; mt++) {
            int r0 = bm + wm + mt * 16 + g;
#pragma unroll
            for (int nt = 0; nt < 8; nt++) {
                int col = bn + wn + nt * 8 + tg * 2;
                int ch = col >> 1;
                float b0 = bias[col], b1 = bias[col + 1];
#pragma unroll
                for (int half_r = 0; half_r < 2; half_r++) {
                    int r = r0 + half_r * 8;
                    float p  = acc[mt][nt][0 + 2 * half_r] + b0;
                    float gt = acc[mt][nt][1 + 2 * half_r] + b1;
                    float xo = __half2float(A[(size_t)r * DD + ch]);
                    float gate = 1.0f / (1.0f + __expf(-gt));
                    float v = gate * xo + (1.0f - gate) * fmaxf(p, 0.0f);
                    Ch[(size_t)r * DD + ch] = __float2half_rn(v);
                }
            }
        }
    } else {
        // mode 3: final highway layer -> write fp32 output tuple directly.
        // out row stride 1024; side z selects column half; duplicate copy.
        float* O = (float*)C;
        const int out_size = aux;
#pragma unroll
        for (int mt = 0; mt < 4; mt++) {
            int r0 = bm + wm + mt * 16 + g;
#pragma unroll
            for (int nt = 0; nt < 8; nt++) {
                int col = bn + wn + nt * 8 + tg * 2;
                int ch = col >> 1;
                float b0 = bias[col], b1 = bias[col + 1];
#pragma unroll
                for (int half_r = 0; half_r < 2; half_r++) {
                    int r = r0 + half_r * 8;
                    float p  = acc[mt][nt][0 + 2 * half_r] + b0;
                    float gt = acc[mt][nt][1 + 2 * half_r] + b1;
                    float xo = __half2float(A[(size_t)r * DD + ch]);
                    float gate = 1.0f / (1.0f + __expf(-gt));
                    float v = gate * xo + (1.0f - gate) * fmaxf(p, 0.0f);
                    size_t idx = (size_t)r * 1024 + z * 512 + ch;
                    O[idx] = v;
                    size_t idx2 = idx + (size_t)MH * 1024;
                    if (idx2 < (size_t)out_size) O[idx2] = v;
                }
            }
        }
    }
}

// ---------------------------------------------------------------------------
// Banded window attention (fp16 QKV, fp32 math), both sides in one launch.
// ---------------------------------------------------------------------------
__device__ __forceinline__ float dot8h(const __half2* a, const __half2* b) {
    float s = 0.0f;
#pragma unroll
    for (int i = 0; i < 4; i++) {
        float2 fa = __half22float2(a[i]);
        float2 fb = __half22float2(b[i]);
        s += fa.x * fb.x + fa.y * fb.y;
    }
    return s;
}

__global__ void attn_kernel(const __half* __restrict__ QKV,
                            __half* __restrict__ out0,
                            __half* __restrict__ out1) {
    const int t = blockIdx.x * 4 + (threadIdx.x >> 6);
    const int h = threadIdx.x & 63;
    const int side = (t >= MQ) ? 1 : 0;
    const int bi = t - side * MQ;
    const int b = bi / NN;
    const int i = bi % NN;
    const int soff = side * 1536;

    __half2 q[4];
    *reinterpret_cast<uint4*>(q) = *reinterpret_cast<const uint4*>(
        QKV + (size_t)bi * 3072 + soff + h * 8);

    const int j0 = side ? i : (i - WID - 1);

    float sc[WINSZ];
    float mx = -1e30f;
#pragma unroll
    for (int tt = 0; tt < WINSZ; tt++) {
        int j = j0 + tt;
        bool valid = (j >= 0) && (j < NN);
        int jc = min(max(j, 0), NN - 1);
        __half2 k[4];
        *reinterpret_cast<uint4*>(k) = *reinterpret_cast<const uint4*>(
            QKV + ((size_t)(b * NN + jc)) * 3072 + soff + 512 + h * 8);
        float s = dot8h(q, k) * 0.35355339059327373f;
        sc[tt] = valid ? s : -1e30f;
        mx = fmaxf(mx, sc[tt]);
    }
    float sum = 0.0f;
#pragma unroll
    for (int tt = 0; tt < WINSZ; tt++) {
        sc[tt] = __expf(sc[tt] - mx);
        sum += sc[tt];
    }
    const float inv = 1.0f / sum;

    float a[8] = {0.f, 0.f, 0.f, 0.f, 0.f, 0.f, 0.f, 0.f};
#pragma unroll
    for (int tt = 0; tt < WINSZ; tt++) {
        int j = j0 + tt;
        int jc = min(max(j, 0), NN - 1);
        __half2 v[4];
        *reinterpret_cast<uint4*>(v) = *reinterpret_cast<const uint4*>(
            QKV + ((size_t)(b * NN + jc)) * 3072 + soff + 1024 + h * 8);
        float p = sc[tt] * inv;
#pragma unroll
        for (int e = 0; e < 4; e++) {
            float2 fv = __half22float2(v[e]);
            a[2 * e]     += p * fv.x;
            a[2 * e + 1] += p * fv.y;
        }
    }
    __half* out = side ? out1 : out0;
    __half2 o[4];
#pragma unroll
    for (int e = 0; e < 4; e++) o[e] = __floats2half2_rn(a[2 * e], a[2 * e + 1]);
    *reinterpret_cast<uint4*>(out + (size_t)bi * DD + h * 8) =
        *reinterpret_cast<uint4*>(o);
}

// ---------------------------------------------------------------------------
// Launch
// ---------------------------------------------------------------------------
extern "C" void kernel_launch(void* const* d_in, const int* in_sizes, int n_in,
                              void* d_out, int out_size) {
    const float* inputs    = (const float*)d_in[0];
    const float* left_pad  = (const float*)d_in[1];
    const float* right_pad = (const float*)d_in[2];
    const float* l_Wqkv    = (const float*)d_in[3];
    const float* l_bqkv    = (const float*)d_in[4];
    const float* l_Wo      = (const float*)d_in[5];
    const float* l_bo      = (const float*)d_in[6];
    const float* r_Wqkv    = (const float*)d_in[7];
    const float* r_bqkv    = (const float*)d_in[8];
    const float* r_Wo      = (const float*)d_in[9];
    const float* r_bo      = (const float*)d_in[10];
    const float* lhw_W     = (const float*)d_in[11];
    const float* lhw_b     = (const float*)d_in[12];
    const float* rhw_W     = (const float*)d_in[13];
    const float* rhw_b     = (const float*)d_in[14];
    float* out = (float*)d_out;

    __half *pX, *pQKV, *pATT0, *pATT1, *pHX0, *pHX1, *pHY0, *pHY1, *pWC;
    float *pB;
    cudaGetSymbolAddress((void**)&pX,    g_X);
    cudaGetSymbolAddress((void**)&pQKV,  g_QKVcat);
    cudaGetSymbolAddress((void**)&pATT0, g_ATT0);
    cudaGetSymbolAddress((void**)&pATT1, g_ATT1);
    cudaGetSymbolAddress((void**)&pHX0,  g_HX0);
    cudaGetSymbolAddress((void**)&pHX1,  g_HX1);
    cudaGetSymbolAddress((void**)&pHY0,  g_HY0);
    cudaGetSymbolAddress((void**)&pHY1,  g_HY1);
    cudaGetSymbolAddress((void**)&pWC,   g_WC);
    cudaGetSymbolAddress((void**)&pB,    g_B);

    cudaFuncSetAttribute(gemm_fused_kernel,
                         cudaFuncAttributeMaxDynamicSharedMemorySize, DYN_SMEM);

    // 0) weights + biases (fp16 / permuted)
    convert_weights_kernel<<<(1048576 + 255) / 256, 256>>>(
        l_Wqkv, r_Wqkv, l_Wo, r_Wo, lhw_W, rhw_W, pWC);
    bias_cat_kernel<<<(7168 + 255) / 256, 256>>>(l_bqkv, r_bqkv, lhw_b, rhw_b, pB);

    // 1) padded fp16 input
    pad_kernel<<<(MQ * (DD / 4) + 255) / 256, 256>>>(inputs, left_pad, right_pad, pX);

    // 2) merged QKV GEMM: [4352,512] @ [3072,512]^T (both sides)
    gemm_fused_kernel<<<dim3(3072 / 256, MQ / 128, 1), 256, DYN_SMEM>>>(
        pX, pX, pWC, pWC, pB, pB, pQKV, pQKV, 3072, 0, 0);

    // 3) windowed attention, both sides
    attn_kernel<<<(2 * MQ) / 4, 256>>>(pQKV, pATT0, pATT1);

    // 4) Wo GEMM + slice, both sides via z
    gemm_fused_kernel<<<dim3(DD / 256, MQ / 128, 2), 256, DYN_SMEM>>>(
        pATT0, pATT1, pWC + 1572864, pWC + 1835008, l_bo, r_bo,
        pHX0, pHX1, DD, 1, 0);

    // 5) highway layer 0: HX -> HY (half)
    gemm_fused_kernel<<<dim3(1024 / 256, MH / 128, 2), 256, DYN_SMEM>>>(
        pHX0, pHX1, pWC + 2097152, pWC + 3145728,
        pB + 3072, pB + 3072 + 2048, pHY0, pHY1, 1024, 2, 0);

    // 6) highway layer 1: HY -> d_out directly (fp32, both tuple copies)
    gemm_fused_kernel<<<dim3(1024 / 256, MH / 128, 2), 256, DYN_SMEM>>>(
        pHY0, pHY1, pWC + 2097152 + 524288, pWC + 3145728 + 524288,
        pB + 3072 + 1024, pB + 3072 + 2048 + 1024, out, out,
        1024, 3, out_size);
}

// round 17
// speedup vs baseline: 1.2304x; 1.2304x over previous
#include <cuda_runtime.h>
#include <cuda_fp16.h>
#include <cstdint>
#include <math.h>

// ---------------------------------------------------------------------------
// Problem constants
// ---------------------------------------------------------------------------
#define BB    8
#define SS    512
#define DD    512
#define WID   16
#define NN    (SS + 2 * WID)      // 544
#define MQ    (BB * NN)           // 4352
#define MH    (BB * SS)           // 4096
#define KDIM  512
#define WINSZ (WID + 2)           // 18

// GEMM tiling: 128x128 tile, BK=32 (fp16), 3-stage cp.async ring
#define STRH     40                         // smem row stride in halfs
#define A_BYTES  (128 * STRH * 2)           // 10240
#define STG_BYTES (2 * A_BYTES)             // 20480 (A tile + W tile)
#define NSTG     3
#define DYN_SMEM (NSTG * STG_BYTES)         // 61440

// ---------------------------------------------------------------------------
// Scratch (static device memory; allocation is forbidden)
// ---------------------------------------------------------------------------
__device__ __half g_X[MQ * DD];
__device__ __half g_QKVcat[MQ * 3072];
__device__ __half g_ATT0[MQ * DD];
__device__ __half g_ATT1[MQ * DD];
__device__ __half g_HX0[MH * DD];
__device__ __half g_HX1[MH * DD];
__device__ __half g_HY0[MH * DD];
__device__ __half g_HY1[MH * DD];
// fp16 weights, packed (half units):
//  [0]        l_Wqkv  1536*512
//  [786432]   r_Wqkv
//  [1572864]  l_Wo     512*512
//  [1835008]  r_Wo
//  [2097152]  lhw_W   2*1024*512  (rows interleaved: 2c=proj_c, 2c+1=gate_c)
//  [3145728]  rhw_W
__device__ __half g_WC[4194304];
// fp32 biases: [0..3071] qkv cat (l then r); [3072..7167] hw interleaved
__device__ float g_B[7168];

// ---------------------------------------------------------------------------
// Convert weights to fp16, packed into g_WC
// ---------------------------------------------------------------------------
__global__ void convert_weights_kernel(const float* __restrict__ lqkv,
                                       const float* __restrict__ rqkv,
                                       const float* __restrict__ lwo,
                                       const float* __restrict__ rwo,
                                       const float* __restrict__ lhw,
                                       const float* __restrict__ rhw,
                                       __half* __restrict__ out) {
    int t = blockIdx.x * blockDim.x + threadIdx.x;
    if (t >= 1048576) return;
    const float* src;
    int loc;
    if (t < 196608)      { src = lqkv; loc = t; }
    else if (t < 393216) { src = rqkv; loc = t - 196608; }
    else if (t < 458752) { src = lwo;  loc = t - 393216; }
    else if (t < 524288) { src = rwo;  loc = t - 458752; }
    else {
        int u = t - 524288;
        int side  = u / 262144;
        int v     = u % 262144;
        int layer = v / 131072;
        int w     = v % 131072;
        int j     = w / 128;           // dest row (interleaved proj/gate)
        int c4    = w % 128;
        int srow  = (j & 1) ? (512 + (j >> 1)) : (j >> 1);
        src = side ? rhw : lhw;
        loc = layer * 131072 + srow * 128 + c4;
    }
    float4 v = reinterpret_cast<const float4*>(src)[loc];
    __half2 h0 = __floats2half2_rn(v.x, v.y);
    __half2 h1 = __floats2half2_rn(v.z, v.w);
    uint2 pk = make_uint2(*(uint32_t*)&h0, *(uint32_t*)&h1);
    *reinterpret_cast<uint2*>(out + (size_t)t * 4) = pk;
}

__global__ void bias_cat_kernel(const float* __restrict__ lbq,
                                const float* __restrict__ rbq,
                                const float* __restrict__ lhb,
                                const float* __restrict__ rhb,
                                float* __restrict__ B) {
    int t = blockIdx.x * blockDim.x + threadIdx.x;
    if (t >= 7168) return;
    if (t < 1536)       B[t] = lbq[t];
    else if (t < 3072)  B[t] = rbq[t - 1536];
    else {
        int u = t - 3072;
        int side  = u >> 11;
        int layer = (u >> 10) & 1;
        int j     = u & 1023;
        int c     = j >> 1;
        int srcj  = (j & 1) ? (512 + c) : c;
        const float* hb = side ? rhb : lhb;
        B[t] = hb[layer * 1024 + srcj];
    }
}

// ---------------------------------------------------------------------------
// Padded input -> fp16
// ---------------------------------------------------------------------------
__global__ void pad_kernel(const float* __restrict__ inp,
                           const float* __restrict__ lp,
                           const float* __restrict__ rp,
                           __half* __restrict__ X) {
    int t = blockIdx.x * blockDim.x + threadIdx.x;     // float4 index
    const int TOT = MQ * (DD / 4);
    if (t >= TOT) return;
    int row = t / (DD / 4);
    int c4  = t % (DD / 4);
    int b = row / NN;
    int n = row % NN;
    float4 v;
    if (n < WID) {
        v = reinterpret_cast<const float4*>(lp)[n * (DD / 4) + c4];
    } else if (n >= WID + SS) {
        v = reinterpret_cast<const float4*>(rp)[(n - WID - SS) * (DD / 4) + c4];
    } else {
        v = reinterpret_cast<const float4*>(inp)[((size_t)b * SS + (n - WID)) * (DD / 4) + c4];
    }
    __half2 h0 = __floats2half2_rn(v.x, v.y);
    __half2 h1 = __floats2half2_rn(v.z, v.w);
    uint2 pk = make_uint2(*(uint32_t*)&h0, *(uint32_t*)&h1);
    *reinterpret_cast<uint2*>(X + (size_t)t * 4) = pk;
}

// ---------------------------------------------------------------------------
// FP16 mma.sync GEMM: C[M, Nt] = A[M,512]h @ W[Nt,512]h^T (f32 accum),
// fused epilogues. 128x128 tile, BK=32, 8 warps (64x32), ldmatrix,
// 3-stage cp.async ring, ONE __syncthreads per K-step.
//   mode 0: C(half) = acc + bias                  (stride Nt)
//   mode 1: Wo + row-slice [WID,WID+SS) -> C(half, stride 512)
//   mode 2: highway (interleaved proj/gate cols) -> C(half, stride 512)
//   mode 3: highway -> final fp32 output tuple (stride 1024, dup; aux=out_size)
// blockIdx.z selects side.
// ---------------------------------------------------------------------------
__global__ __launch_bounds__(256, 2) void gemm_fused_kernel(
    const __half* __restrict__ A0, const __half* __restrict__ A1,
    const __half* __restrict__ W0, const __half* __restrict__ W1,
    const float* __restrict__ B0, const float* __restrict__ B1,
    void* __restrict__ C0, void* __restrict__ C1,
    int Nt, int mode, int aux) {
    extern __shared__ char dsm[];

    const int z = blockIdx.z;
    const __half* A = z ? A1 : A0;
    const __half* W = z ? W1 : W0;
    const float* bias = z ? B1 : B0;
    void* C = z ? C1 : C0;

    const int bm = blockIdx.y * 128;
    const int bn = blockIdx.x * 128;
    const int tid = threadIdx.x;
    const int lane = tid & 31;
    const int wrp = tid >> 5;
    const int wm = (wrp & 1) * 64;     // warp m offset
    const int wn = (wrp >> 1) * 32;    // warp n offset
    const int g  = lane >> 2;          // epilogue row within 8
    const int tg = lane & 3;

    const uint32_t smemBase = (uint32_t)__cvta_generic_to_shared(dsm);

    // ldmatrix provider byte offsets
    const uint32_t aOff =
        ((wm + (lane & 15)) * STRH + (lane >> 4) * 8) * 2;
    const uint32_t bOff =
        ((wn + ((lane >> 4) & 1) * 8 + (lane & 7)) * STRH + ((lane >> 3) & 1) * 8) * 2;

    float acc[4][4][4];
#pragma unroll
    for (int mt = 0; mt < 4; mt++)
#pragma unroll
        for (int nt = 0; nt < 4; nt++)
#pragma unroll
            for (int r = 0; r < 4; r++) acc[mt][nt][r] = 0.0f;

    // global->smem: per stage 1024 16B-chunks (A 512 + W 512), 4 per thread
    auto issue = [&](int s, int k0) {
        uint32_t base = smemBase + s * STG_BYTES;
#pragma unroll
        for (int i = 0; i < 2; i++) {
            int id = tid + (i << 8);
            int r = id >> 2, c = id & 3;
            uint32_t dst = base + (r * STRH + c * 8) * 2;
            const __half* src = A + (size_t)(bm + r) * KDIM + k0 + c * 8;
            asm volatile("cp.async.cg.shared.global [%0], [%1], 16;"
                         :: "r"(dst), "l"(src));
        }
#pragma unroll
        for (int i = 0; i < 2; i++) {
            int id = tid + (i << 8);
            int r = id >> 2, c = id & 3;
            uint32_t dst = base + A_BYTES + (r * STRH + c * 8) * 2;
            const __half* src = W + (size_t)(bn + r) * KDIM + k0 + c * 8;
            asm volatile("cp.async.cg.shared.global [%0], [%1], 16;"
                         :: "r"(dst), "l"(src));
        }
        asm volatile("cp.async.commit_group;");
    };

    auto compute = [&](int s) {
        const uint32_t aPtr = smemBase + s * STG_BYTES + aOff;
        const uint32_t wPtr = smemBase + s * STG_BYTES + A_BYTES + bOff;
#pragma unroll
        for (int kc = 0; kc < 2; kc++) {           // two k16 chunks in BK=32
            uint32_t a[4][4], b[4][2];
#pragma unroll
            for (int mt = 0; mt < 4; mt++) {
                uint32_t addr = aPtr + mt * (16 * STRH * 2) + kc * 32;
                asm volatile(
                    "ldmatrix.sync.aligned.m8n8.x4.shared.b16 {%0,%1,%2,%3}, [%4];"
                    : "=r"(a[mt][0]), "=r"(a[mt][1]), "=r"(a[mt][2]),
                      "=r"(a[mt][3])
                    : "r"(addr));
            }
#pragma unroll
            for (int ntp = 0; ntp < 2; ntp++) {
                uint32_t addr = wPtr + ntp * (16 * STRH * 2) + kc * 32;
                asm volatile(
                    "ldmatrix.sync.aligned.m8n8.x4.shared.b16 {%0,%1,%2,%3}, [%4];"
                    : "=r"(b[2 * ntp][0]), "=r"(b[2 * ntp][1]),
                      "=r"(b[2 * ntp + 1][0]), "=r"(b[2 * ntp + 1][1])
                    : "r"(addr));
            }
#pragma unroll
            for (int mt = 0; mt < 4; mt++)
#pragma unroll
                for (int nt = 0; nt < 4; nt++)
                    asm volatile(
                        "mma.sync.aligned.m16n8k16.row.col.f32.f16.f16.f32 "
                        "{%0,%1,%2,%3},{%4,%5,%6,%7},{%8,%9},{%0,%1,%2,%3};"
                        : "+f"(acc[mt][nt][0]), "+f"(acc[mt][nt][1]),
                          "+f"(acc[mt][nt][2]), "+f"(acc[mt][nt][3])
                        : "r"(a[mt][0]), "r"(a[mt][1]), "r"(a[mt][2]),
                          "r"(a[mt][3]), "r"(b[nt][0]), "r"(b[nt][1]));
        }
    };

    const int NIT = KDIM / 32;   // 16
    issue(0, 0);
    issue(1, 32);
    for (int it = 0; it < NIT; it++) {
        if (it < NIT - 2)
            asm volatile("cp.async.wait_group 1;");
        else
            asm volatile("cp.async.wait_group 0;");
        __syncthreads();
        if (it + 2 < NIT) issue((it + 2) % NSTG, (it + 2) * 32);
        compute(it % NSTG);
    }

    // ---------------- epilogues ----------------
    if (mode == 0) {
        __half* Ch = (__half*)C;
#pragma unroll
        for (int mt = 0; mt < 4; mt++) {
            int r0 = bm + wm + mt * 16 + g;
#pragma unroll
            for (int nt = 0; nt < 4; nt++) {
                int c = bn + wn + nt * 8 + tg * 2;
                float b0 = bias[c], b1 = bias[c + 1];
                __half2 v0 = __floats2half2_rn(acc[mt][nt][0] + b0,
                                               acc[mt][nt][1] + b1);
                __half2 v1 = __floats2half2_rn(acc[mt][nt][2] + b0,
                                               acc[mt][nt][3] + b1);
                *reinterpret_cast<__half2*>(&Ch[(size_t)r0 * Nt + c]) = v0;
                *reinterpret_cast<__half2*>(&Ch[(size_t)(r0 + 8) * Nt + c]) = v1;
            }
        }
    } else if (mode == 1) {
        // Wo + slice: row r -> (b, n); keep n in [WID, WID+SS); half out
        __half* Ch = (__half*)C;
#pragma unroll
        for (int mt = 0; mt < 4; mt++) {
            int r0 = bm + wm + mt * 16 + g;
#pragma unroll
            for (int half_r = 0; half_r < 2; half_r++) {
                int r = r0 + half_r * 8;
                int b = r / NN;
                int n = r % NN;
                if (n < WID || n >= WID + SS) continue;
                int drow = b * SS + (n - WID);
#pragma unroll
                for (int nt = 0; nt < 4; nt++) {
                    int c = bn + wn + nt * 8 + tg * 2;
                    float b0 = bias[c], b1 = bias[c + 1];
                    __half2 v = __floats2half2_rn(
                        acc[mt][nt][0 + 2 * half_r] + b0,
                        acc[mt][nt][1 + 2 * half_r] + b1);
                    *reinterpret_cast<__half2*>(&Ch[(size_t)drow * DD + c]) = v;
                }
            }
        }
    } else if (mode == 2) {
        // highway: acc pair = (proj, gate) for channel col/2; x_old = A (half)
        __half* Ch = (__half*)C;
#pragma unroll
        for (int mt = 0; mt < 4; mt++) {
            int r0 = bm + wm + mt * 16 + g;
#pragma unroll
            for (int nt = 0; nt < 4; nt++) {
                int col = bn + wn + nt * 8 + tg * 2;
                int ch = col >> 1;
                float b0 = bias[col], b1 = bias[col + 1];
#pragma unroll
                for (int half_r = 0; half_r < 2; half_r++) {
                    int r = r0 + half_r * 8;
                    float p  = acc[mt][nt][0 + 2 * half_r] + b0;
                    float gt = acc[mt][nt][1 + 2 * half_r] + b1;
                    float xo = __half2float(A[(size_t)r * DD + ch]);
                    float gate = 1.0f / (1.0f + __expf(-gt));
                    float v = gate * xo + (1.0f - gate) * fmaxf(p, 0.0f);
                    Ch[(size_t)r * DD + ch] = __float2half_rn(v);
                }
            }
        }
    } else {
        // mode 3: final highway layer -> write fp32 output tuple directly.
        // out row stride 1024; side z selects column half; duplicate copy.
        float* O = (float*)C;
        const int out_size = aux;
#pragma unroll
        for (int mt = 0; mt < 4; mt++) {
            int r0 = bm + wm + mt * 16 + g;
#pragma unroll
            for (int nt = 0; nt < 4; nt++) {
                int col = bn + wn + nt * 8 + tg * 2;
                int ch = col >> 1;
                float b0 = bias[col], b1 = bias[col + 1];
#pragma unroll
                for (int half_r = 0; half_r < 2; half_r++) {
                    int r = r0 + half_r * 8;
                    float p  = acc[mt][nt][0 + 2 * half_r] + b0;
                    float gt = acc[mt][nt][1 + 2 * half_r] + b1;
                    float xo = __half2float(A[(size_t)r * DD + ch]);
                    float gate = 1.0f / (1.0f + __expf(-gt));
                    float v = gate * xo + (1.0f - gate) * fmaxf(p, 0.0f);
                    size_t idx = (size_t)r * 1024 + z * 512 + ch;
                    O[idx] = v;
                    size_t idx2 = idx + (size_t)MH * 1024;
                    if (idx2 < (size_t)out_size) O[idx2] = v;
                }
            }
        }
    }
}

// ---------------------------------------------------------------------------
// Banded window attention (fp16 QKV, fp32 math), both sides in one launch.
// ---------------------------------------------------------------------------
__device__ __forceinline__ float dot8h(const __half2* a, const __half2* b) {
    float s = 0.0f;
#pragma unroll
    for (int i = 0; i < 4; i++) {
        float2 fa = __half22float2(a[i]);
        float2 fb = __half22float2(b[i]);
        s += fa.x * fb.x + fa.y * fb.y;
    }
    return s;
}

__global__ void attn_kernel(const __half* __restrict__ QKV,
                            __half* __restrict__ out0,
                            __half* __restrict__ out1) {
    const int t = blockIdx.x * 4 + (threadIdx.x >> 6);
    const int h = threadIdx.x & 63;
    const int side = (t >= MQ) ? 1 : 0;
    const int bi = t - side * MQ;
    const int b = bi / NN;
    const int i = bi % NN;
    const int soff = side * 1536;

    __half2 q[4];
    *reinterpret_cast<uint4*>(q) = *reinterpret_cast<const uint4*>(
        QKV + (size_t)bi * 3072 + soff + h * 8);

    const int j0 = side ? i : (i - WID - 1);

    float sc[WINSZ];
    float mx = -1e30f;
#pragma unroll
    for (int tt = 0; tt < WINSZ; tt++) {
        int j = j0 + tt;
        bool valid = (j >= 0) && (j < NN);
        int jc = min(max(j, 0), NN - 1);
        __half2 k[4];
        *reinterpret_cast<uint4*>(k) = *reinterpret_cast<const uint4*>(
            QKV + ((size_t)(b * NN + jc)) * 3072 + soff + 512 + h * 8);
        float s = dot8h(q, k) * 0.35355339059327373f;
        sc[tt] = valid ? s : -1e30f;
        mx = fmaxf(mx, sc[tt]);
    }
    float sum = 0.0f;
#pragma unroll
    for (int tt = 0; tt < WINSZ; tt++) {
        sc[tt] = __expf(sc[tt] - mx);
        sum += sc[tt];
    }
    const float inv = 1.0f / sum;

    float a[8] = {0.f, 0.f, 0.f, 0.f, 0.f, 0.f, 0.f, 0.f};
#pragma unroll
    for (int tt = 0; tt < WINSZ; tt++) {
        int j = j0 + tt;
        int jc = min(max(j, 0), NN - 1);
        __half2 v[4];
        *reinterpret_cast<uint4*>(v) = *reinterpret_cast<const uint4*>(
            QKV + ((size_t)(b * NN + jc)) * 3072 + soff + 1024 + h * 8);
        float p = sc[tt] * inv;
#pragma unroll
        for (int e = 0; e < 4; e++) {
            float2 fv = __half22float2(v[e]);
            a[2 * e]     += p * fv.x;
            a[2 * e + 1] += p * fv.y;
        }
    }
    __half* out = side ? out1 : out0;
    __half2 o[4];
#pragma unroll
    for (int e = 0; e < 4; e++) o[e] = __floats2half2_rn(a[2 * e], a[2 * e + 1]);
    *reinterpret_cast<uint4*>(out + (size_t)bi * DD + h * 8) =
        *reinterpret_cast<uint4*>(o);
}

// ---------------------------------------------------------------------------
// Launch
// ---------------------------------------------------------------------------
extern "C" void kernel_launch(void* const* d_in, const int* in_sizes, int n_in,
                              void* d_out, int out_size) {
    const float* inputs    = (const float*)d_in[0];
    const float* left_pad  = (const float*)d_in[1];
    const float* right_pad = (const float*)d_in[2];
    const float* l_Wqkv    = (const float*)d_in[3];
    const float* l_bqkv    = (const float*)d_in[4];
    const float* l_Wo      = (const float*)d_in[5];
    const float* l_bo      = (const float*)d_in[6];
    const float* r_Wqkv    = (const float*)d_in[7];
    const float* r_bqkv    = (const float*)d_in[8];
    const float* r_Wo      = (const float*)d_in[9];
    const float* r_bo      = (const float*)d_in[10];
    const float* lhw_W     = (const float*)d_in[11];
    const float* lhw_b     = (const float*)d_in[12];
    const float* rhw_W     = (const float*)d_in[13];
    const float* rhw_b     = (const float*)d_in[14];
    float* out = (float*)d_out;

    __half *pX, *pQKV, *pATT0, *pATT1, *pHX0, *pHX1, *pHY0, *pHY1, *pWC;
    float *pB;
    cudaGetSymbolAddress((void**)&pX,    g_X);
    cudaGetSymbolAddress((void**)&pQKV,  g_QKVcat);
    cudaGetSymbolAddress((void**)&pATT0, g_ATT0);
    cudaGetSymbolAddress((void**)&pATT1, g_ATT1);
    cudaGetSymbolAddress((void**)&pHX0,  g_HX0);
    cudaGetSymbolAddress((void**)&pHX1,  g_HX1);
    cudaGetSymbolAddress((void**)&pHY0,  g_HY0);
    cudaGetSymbolAddress((void**)&pHY1,  g_HY1);
    cudaGetSymbolAddress((void**)&pWC,   g_WC);
    cudaGetSymbolAddress((void**)&pB,    g_B);

    cudaFuncSetAttribute(gemm_fused_kernel,
                         cudaFuncAttributeMaxDynamicSharedMemorySize, DYN_SMEM);

    // 0) weights + biases (fp16 / permuted)
    convert_weights_kernel<<<(1048576 + 255) / 256, 256>>>(
        l_Wqkv, r_Wqkv, l_Wo, r_Wo, lhw_W, rhw_W, pWC);
    bias_cat_kernel<<<(7168 + 255) / 256, 256>>>(l_bqkv, r_bqkv, lhw_b, rhw_b, pB);

    // 1) padded fp16 input
    pad_kernel<<<(MQ * (DD / 4) + 255) / 256, 256>>>(inputs, left_pad, right_pad, pX);

    // 2) merged QKV GEMM: [4352,512] @ [3072,512]^T (both sides)
    gemm_fused_kernel<<<dim3(3072 / 128, MQ / 128, 1), 256, DYN_SMEM>>>(
        pX, pX, pWC, pWC, pB, pB, pQKV, pQKV, 3072, 0, 0);

    // 3) windowed attention, both sides
    attn_kernel<<<(2 * MQ) / 4, 256>>>(pQKV, pATT0, pATT1);

    // 4) Wo GEMM + slice, both sides via z
    gemm_fused_kernel<<<dim3(DD / 128, MQ / 128, 2), 256, DYN_SMEM>>>(
        pATT0, pATT1, pWC + 1572864, pWC + 1835008, l_bo, r_bo,
        pHX0, pHX1, DD, 1, 0);

    // 5) highway layer 0: HX -> HY (half)
    gemm_fused_kernel<<<dim3(1024 / 128, MH / 128, 2), 256, DYN_SMEM>>>(
        pHX0, pHX1, pWC + 2097152, pWC + 3145728,
        pB + 3072, pB + 3072 + 2048, pHY0, pHY1, 1024, 2, 0);

    // 6) highway layer 1: HY -> d_out directly (fp32, both tuple copies)
    gemm_fused_kernel<<<dim3(1024 / 128, MH / 128, 2), 256, DYN_SMEM>>>(
        pHY0, pHY1, pWC + 2097152 + 524288, pWC + 3145728 + 524288,
        pB + 3072 + 1024, pB + 3072 + 2048 + 1024, out, out,
        1024, 3, out_size);
}